// round 17
// baseline (speedup 1.0000x reference)
#include <cuda_runtime.h>
#include <cstdint>

#define NUM_USER   4096
#define NUM_ITEM   16384
#define NUM_HIDDEN 64
#define BATCH      1024
#define SETLEN     50
#define NJ         (BATCH * SETLEN)              // 51200 scatter updates

#define PLANE      ((size_t)NUM_USER * NUM_ITEM) // 67,108,864 cells per plane
#define LPJ        8                             // lanes per update (measured optimum)

// Persistent device state. g_nnz: zero at the start of every launch/replay
// (compute_kernel resets it). g_cellv/g_predv: fully rewritten every launch.
__device__ unsigned int g_nnz;
__device__ unsigned int g_cellv[NJ];             // cell per update j
__device__ float        g_predv[NJ];             // dot product per update j

// 32B load (two float4s) with L2 evict-last (legal sm_100a shape .v4.b64).
__device__ __forceinline__ void ldg32B_evict_last(const float4* p,
                                                  float4& v0, float4& v1) {
    unsigned long long x0, x1, x2, x3;
    asm volatile("ld.global.nc.L2::evict_last.v4.b64 {%0,%1,%2,%3}, [%4];"
                 : "=l"(x0), "=l"(x1), "=l"(x2), "=l"(x3)
                 : "l"(p));
    v0.x = __uint_as_float((unsigned int)x0);
    v0.y = __uint_as_float((unsigned int)(x0 >> 32));
    v0.z = __uint_as_float((unsigned int)x1);
    v0.w = __uint_as_float((unsigned int)(x1 >> 32));
    v1.x = __uint_as_float((unsigned int)x2);
    v1.y = __uint_as_float((unsigned int)(x2 >> 32));
    v1.z = __uint_as_float((unsigned int)x3);
    v1.w = __uint_as_float((unsigned int)(x3 >> 32));
}

// ---------------------------------------------------------------------------
// Branch A, k1: arbitration. Thread j tags label[cell] with j+1 via
// atomicMax -> surviving tag = max j = last-write-wins in (b,l) row-major
// order (XLA scatter semantics). First toucher (old==0; label plane zeroed
// by the preceding memset) counts the unique cell (warp-ballot aggregated).
// ---------------------------------------------------------------------------
__global__ void __launch_bounds__(512)
tag_kernel(const int* __restrict__ idx_user,
           const int* __restrict__ item_sets,
           float* __restrict__ out) {
    int j = blockIdx.x * blockDim.x + threadIdx.x;
    if (j >= NJ) return;
    int b = j / SETLEN;
    unsigned int u    = (unsigned int)__ldg(idx_user + b);
    unsigned int it   = (unsigned int)__ldg(item_sets + j);
    unsigned int cell = u * NUM_ITEM + it;

    int old = atomicMax((int*)(out + PLANE) + cell, j + 1);

    unsigned int m = __ballot_sync(0xFFFFFFFFu, old == 0);
    if ((threadIdx.x & 31) == 0 && m) atomicAdd(&g_nnz, __popc(m));
}

// ---------------------------------------------------------------------------
// Branch A, k2: compute (R16's resolve, pred redirected to scratch since
// the pred plane's memset runs CONCURRENTLY in branch B).
//  - 8 lanes per update: 32B evict-last embed loads, butterfly reduce.
//  - label: lane 0 reads the final tag; the unique winner (tag == j+1)
//    overwrites the tag with its rating (label plane is ready).
//  - pred: lane 0 stashes (cell, dot) in scratch for the post-join patch.
//  - global thread 0 emits sparsity and restores g_nnz = 0.
// ---------------------------------------------------------------------------
__global__ void __launch_bounds__(256)
compute_kernel(const int*   __restrict__ idx_user,
               const int*   __restrict__ item_sets,
               const float* __restrict__ ratings,
               const float* __restrict__ embed_user,
               const float* __restrict__ embed_item,
               float* __restrict__ out) {
    int t = blockIdx.x * blockDim.x + threadIdx.x;
    if (t == 0) {
        out[2 * PLANE] = (float)((double)PLANE / (double)g_nnz);
        g_nnz = 0u;                              // self-cleaning invariant
    }
    int j = t >> 3;                              // update index
    int r = t & (LPJ - 1);                       // lane within 8-group
    if (j >= NJ) return;

    int b = j / SETLEN;
    unsigned int u    = (unsigned int)__ldg(idx_user + b);
    unsigned int it   = (unsigned int)__ldg(item_sets + j);
    unsigned int cell = u * NUM_ITEM + it;

    int   tag = 0;
    float rat = 0.f;
    if (r == 0) {
        tag = ((const int*)(out + PLANE))[cell];
        rat = __ldg(ratings + j);
    }

    const float4* ur = (const float4*)(embed_user + (size_t)u  * NUM_HIDDEN);
    const float4* ir = (const float4*)(embed_item + (size_t)it * NUM_HIDDEN);
    float4 a0, a1, c0, c1;
    ldg32B_evict_last(ur + 2*r, a0, a1);
    ldg32B_evict_last(ir + 2*r, c0, c1);
    float s  = fmaf(a0.x,c0.x, fmaf(a0.y,c0.y, fmaf(a0.z,c0.z, a0.w*c0.w)));
    s       += fmaf(a1.x,c1.x, fmaf(a1.y,c1.y, fmaf(a1.z,c1.z, a1.w*c1.w)));

    s += __shfl_xor_sync(0xFFFFFFFFu, s, 4, LPJ);
    s += __shfl_xor_sync(0xFFFFFFFFu, s, 2, LPJ);
    s += __shfl_xor_sync(0xFFFFFFFFu, s, 1, LPJ);

    if (r == 0) {
        g_cellv[j] = cell;                       // stash for post-join patch
        g_predv[j] = s;
        if (tag == j + 1)
            out[PLANE + cell] = rat;             // label: unique winner
    }
}

// ---------------------------------------------------------------------------
// Post-join patch: scatter stashed preds into the (now zeroed) pred plane.
// No winner check needed — duplicates of a cell carry identical dot values,
// so racing stores write identical bits (benign).
// ---------------------------------------------------------------------------
__global__ void __launch_bounds__(512)
patch_kernel(float* __restrict__ out) {
    int j = blockIdx.x * blockDim.x + threadIdx.x;
    if (j >= NJ) return;
    out[g_cellv[j]] = g_predv[j];
}

// ---------------------------------------------------------------------------
// Fork-join, branch order reversed vs the failed R5 attempt: the tiny
// branch-A kernel nodes are CREATED BEFORE the branch-B memset node, so
// their small grids launch first and the 256MB pred-plane memset fills the
// remaining SMs — tag+compute (~11us) hide under the ~40us fill.
//   stream0: memset(label) -> tag -> compute ----\
//   side:                  \-> memset(pred) ------+-> patch
// ---------------------------------------------------------------------------
extern "C" void kernel_launch(void* const* d_in, const int* in_sizes, int n_in,
                              void* d_out, int out_size) {
    const int*   idx_user   = (const int*)  d_in[0];
    const int*   item_sets  = (const int*)  d_in[1];
    const float* rating     = (const float*)d_in[2];
    const float* embed_user = (const float*)d_in[3];
    const float* embed_item = (const float*)d_in[4];
    float* out = (float*)d_out;

    static cudaStream_t side = nullptr;
    static cudaEvent_t  ev_fork = nullptr, ev_done = nullptr;
    if (side == nullptr) {
        cudaStreamCreateWithFlags(&side, cudaStreamNonBlocking);
        cudaEventCreateWithFlags(&ev_fork, cudaEventDisableTiming);
        cudaEventCreateWithFlags(&ev_done, cudaEventDisableTiming);
    }

    // Serial: zero the LABEL plane (tag needs it).
    cudaMemsetAsync(out + PLANE, 0, PLANE * sizeof(float), 0);
    cudaEventRecord(ev_fork, 0);

    // Branch A (created FIRST -> launches first): tag + compute.
    tag_kernel    <<<(NJ + 511) / 512, 512>>>(idx_user, item_sets, out);
    compute_kernel<<<(NJ * LPJ + 255) / 256, 256>>>(idx_user, item_sets, rating,
                                                    embed_user, embed_item, out);

    // Branch B (created after): zero the PRED plane concurrently.
    cudaStreamWaitEvent(side, ev_fork, 0);
    cudaMemsetAsync(out, 0, PLANE * sizeof(float), side);
    cudaEventRecord(ev_done, side);

    // Join: patch preds after both the pred memset and compute finished.
    cudaStreamWaitEvent(0, ev_done, 0);
    patch_kernel<<<(NJ + 511) / 512, 512>>>(out);
}